// round 8
// baseline (speedup 1.0000x reference)
#include <cuda_runtime.h>
#include <math_constants.h>

#define WSZ    8
#define P2     64
#define CH     128
#define W1G    32
#define NWPB   1024
#define BATCH  8
#define NWIN   (BATCH*NWPB)
#define HD     32
#define NH     4
#define SHIFT  4
#define PSTR   132
#define NTHR   512

__device__ __forceinline__ int swz4(int tok, int c4) { return tok * 32 + (c4 ^ (tok & 7)); }
__device__ __forceinline__ int swz(int tok, int ch) {
    return tok * 128 + ((((ch >> 2) ^ (tok & 7))) << 2) + (ch & 3);
}

// ---------------- scratch ----------------
__device__ float g_xw [(size_t)NWIN * P2 * CH];
__device__ float g_off[NWIN * P2 * 2];
__device__ float g_oi [NWIN * 2];

// ---------------- kernel 1 ----------------
__global__ __launch_bounds__(256)
void k_prep(const float* __restrict__ x,
            const float* __restrict__ wi_w, const float* __restrict__ wi_b,
            const float* __restrict__ w1_w, const float* __restrict__ w1_b,
            const float* __restrict__ w2_w, const float* __restrict__ w2_b)
{
    __shared__ float sT[P2 * PSTR];
    __shared__ float sT1[P2 * 2];

    const int win = blockIdx.x;
    const int b   = win >> 10;
    const int wr  = win & 1023;
    const int wi  = wr >> 5;
    const int wj  = wr & 31;
    const int tid = threadIdx.x;

    float4* gx4 = (float4*)(g_xw + (size_t)win * P2 * CH);

    for (int i4 = tid; i4 < P2 * CH / 4; i4 += 256) {
        const int tok = i4 >> 5, c4 = i4 & 31;
        const int pi = tok >> 3, pj = tok & 7;
        const int r = (wi * 8 + pi + SHIFT) & 255;
        const int c = (wj * 8 + pj + SHIFT) & 255;
        const float4 v = *(const float4*)(x + (size_t)((((b << 8) + r) << 8) + c) * CH + c4 * 4);
        *(float4*)(sT + tok * PSTR + c4 * 4) = v;
        gx4[i4] = v;
    }
    __syncthreads();

    {
        const int kind = tid >> 7;
        const int rem  = tid & 127;
        const int tok  = rem >> 1;
        const int d    = rem & 1;
        const float* w = kind ? w1_w : wi_w;
        float acc = 0.f;
        #pragma unroll 8
        for (int ch = 0; ch < 128; ++ch)
            acc = fmaf(sT[tok * PSTR + ch], w[ch * 2 + d], acc);
        if (kind) sT1[tok * 2 + d] = acc + w1_b[d];
        else      g_off[win * 128 + tok * 2 + d] = acc + wi_b[d];
    }
    __syncthreads();

    if (tid < 2) {
        float acc = w2_b[tid];
        for (int f = 0; f < 128; ++f)
            acc = fmaf(sT1[f], w2_w[f * 2 + tid], acc);
        g_oi[win * 2 + tid] = acc;
    }
}

#define GEMM8_FMAS(a)                                     \
    acc[r][0] = fmaf(a.x, w0.x, acc[r][0]);               \
    acc[r][1] = fmaf(a.x, w0.y, acc[r][1]);               \
    acc[r][2] = fmaf(a.x, w0.z, acc[r][2]);               \
    acc[r][3] = fmaf(a.x, w0.w, acc[r][3]);               \
    acc[r][0] = fmaf(a.y, w1.x, acc[r][0]);               \
    acc[r][1] = fmaf(a.y, w1.y, acc[r][1]);               \
    acc[r][2] = fmaf(a.y, w1.z, acc[r][2]);               \
    acc[r][3] = fmaf(a.y, w1.w, acc[r][3]);               \
    acc[r][0] = fmaf(a.z, w2.x, acc[r][0]);               \
    acc[r][1] = fmaf(a.z, w2.y, acc[r][1]);               \
    acc[r][2] = fmaf(a.z, w2.z, acc[r][2]);               \
    acc[r][3] = fmaf(a.z, w2.w, acc[r][3]);               \
    acc[r][0] = fmaf(a.w, w3.x, acc[r][0]);               \
    acc[r][1] = fmaf(a.w, w3.y, acc[r][1]);               \
    acc[r][2] = fmaf(a.w, w3.z, acc[r][2]);               \
    acc[r][3] = fmaf(a.w, w3.w, acc[r][3]);

// 64x128 GEMM slice: warp g computes rows g*8..g*8+7, lane tx cols 4tx..4tx+3.
// A from swizzled smem.
__device__ __forceinline__
void gemm8s(const float* __restrict__ in_s, const float* __restrict__ w,
            int wstride, int woff, const float* __restrict__ bias, int boff,
            float* __restrict__ out_s, int g, int tx)
{
    float acc[8][4] = {};
    const int r0 = g * 8;
    const float* wbase = w + woff + tx * 4;
    const float4* inv4 = (const float4*)in_s;
    #pragma unroll 2
    for (int c4 = 0; c4 < 32; ++c4) {
        const int ci = c4 * 4;
        const float4 w0 = __ldg((const float4*)(wbase + (size_t)(ci + 0) * wstride));
        const float4 w1 = __ldg((const float4*)(wbase + (size_t)(ci + 1) * wstride));
        const float4 w2 = __ldg((const float4*)(wbase + (size_t)(ci + 2) * wstride));
        const float4 w3 = __ldg((const float4*)(wbase + (size_t)(ci + 3) * wstride));
        #pragma unroll
        for (int r = 0; r < 8; ++r) {
            const float4 a = inv4[swz4(r0 + r, c4)];
            GEMM8_FMAS(a)
        }
    }
    const float4 bv = *(const float4*)(bias + boff + tx * 4);
    float4* outv4 = (float4*)out_s;
    #pragma unroll
    for (int r = 0; r < 8; ++r) {
        float4 o;
        o.x = acc[r][0] + bv.x; o.y = acc[r][1] + bv.y;
        o.z = acc[r][2] + bv.z; o.w = acc[r][3] + bv.w;
        outv4[swz4(r0 + r, tx)] = o;
    }
}

// same, A streamed from gmem (linear [tok][ch], broadcast)
__device__ __forceinline__
void gemm8g(const float* __restrict__ in_g, const float* __restrict__ w,
            int wstride, int woff, const float* __restrict__ bias, int boff,
            float* __restrict__ out_s, int g, int tx)
{
    float acc[8][4] = {};
    const int r0 = g * 8;
    const float* wbase = w + woff + tx * 4;
    #pragma unroll 2
    for (int c4 = 0; c4 < 32; ++c4) {
        const int ci = c4 * 4;
        const float4 w0 = __ldg((const float4*)(wbase + (size_t)(ci + 0) * wstride));
        const float4 w1 = __ldg((const float4*)(wbase + (size_t)(ci + 1) * wstride));
        const float4 w2 = __ldg((const float4*)(wbase + (size_t)(ci + 2) * wstride));
        const float4 w3 = __ldg((const float4*)(wbase + (size_t)(ci + 3) * wstride));
        #pragma unroll
        for (int r = 0; r < 8; ++r) {
            const float4 a = __ldg((const float4*)(in_g + (r0 + r) * CH + ci));
            GEMM8_FMAS(a)
        }
    }
    const float4 bv = *(const float4*)(bias + boff + tx * 4);
    float4* outv4 = (float4*)out_s;
    #pragma unroll
    for (int r = 0; r < 8; ++r) {
        float4 o;
        o.x = acc[r][0] + bv.x; o.y = acc[r][1] + bv.y;
        o.z = acc[r][2] + bv.z; o.w = acc[r][3] + bv.w;
        outv4[swz4(r0 + r, tx)] = o;
    }
}

// ---------------- kernel 2 ----------------
__global__ __launch_bounds__(NTHR, 2)
void k_main(const float* __restrict__ rpp,
            const float* __restrict__ q_w,  const float* __restrict__ q_b,
            const float* __restrict__ kv_w, const float* __restrict__ kv_b,
            const float* __restrict__ o_w,  const float* __restrict__ o_b,
            float* __restrict__ out)
{
    extern __shared__ float sm[];
    float* bufA = sm;            // q -> attn-out
    float* bufB = bufA + 8192;   // xd2 -> k (in-place)
    float* bufC = bufB + 8192;   // xd -> v
    float* sSim = bufC + 8192;   // 64x64

    const int win = blockIdx.x;
    const int b   = win >> 10;
    const int wr  = win & 1023;
    const int wi  = wr >> 5;
    const int wj  = wr & 31;
    const int tid = threadIdx.x;
    const int wp  = tid >> 5, tx = tid & 31;

    // ---- inter-window bilinear blend -> bufC (xd) ----
    {
        const float ox = __ldg(g_oi + win * 2 + 0), oy = __ldg(g_oi + win * 2 + 1);
        const float gxp = (float)wj + ox, gyp = (float)wi + oy;
        const float x0f = floorf(gxp), y0f = floorf(gyp);
        const float fx = gxp - x0f, fy = gyp - y0f;
        const int x0 = (int)x0f, y0 = (int)y0f;
        const float wgt[4] = {(1.f - fx) * (1.f - fy), fx * (1.f - fy),
                              (1.f - fx) * fy,          fx * fy};
        const float4* nb[4];
        float nww[4];
        #pragma unroll
        for (int k = 0; k < 4; ++k) {
            const int xx = x0 + (k & 1), yy = y0 + (k >> 1);
            const bool valid = (xx >= 0) && (xx < W1G) && (yy >= 0) && (yy < W1G);
            nb[k]  = (const float4*)(valid ? (g_xw + (size_t)((b << 10) + (yy << 5) + xx) * P2 * CH)
                                           : g_xw);
            nww[k] = valid ? wgt[k] : 0.f;
        }
        float4* outv4 = (float4*)bufC;
        for (int i4 = tid; i4 < 2048; i4 += NTHR) {
            const float4 v0 = __ldg(nb[0] + i4), v1 = __ldg(nb[1] + i4);
            const float4 v2 = __ldg(nb[2] + i4), v3 = __ldg(nb[3] + i4);
            float4 r;
            r.x = nww[0]*v0.x + nww[1]*v1.x + nww[2]*v2.x + nww[3]*v3.x;
            r.y = nww[0]*v0.y + nww[1]*v1.y + nww[2]*v2.y + nww[3]*v3.y;
            r.z = nww[0]*v0.z + nww[1]*v1.z + nww[2]*v2.z + nww[3]*v3.z;
            r.w = nww[0]*v0.w + nww[1]*v1.w + nww[2]*v2.w + nww[3]*v3.w;
            outv4[swz4(i4 >> 5, i4 & 31)] = r;
        }
    }
    __syncthreads();

    // ---- intra-window gather bufC -> bufB (xd2) ----
    {
        const float4* inv4 = (const float4*)bufC;
        float4* outv4 = (float4*)bufB;
        #pragma unroll
        for (int it = 0; it < 4; ++it) {
            const int i4 = tid + it * NTHR;
            const int tok = i4 >> 5, c4 = i4 & 31;
            const int pi = tok >> 3, pj = tok & 7;
            const float o0 = __ldg(g_off + win * 128 + tok * 2);
            const float o1 = __ldg(g_off + win * 128 + tok * 2 + 1);
            const float gx2 = (float)pj + o0, gy2 = (float)pi + o1;
            const float xf = floorf(gx2), yf = floorf(gy2);
            const float fx = gx2 - xf, fy = gy2 - yf;
            const int x0 = (int)xf, y0 = (int)yf;
            const float ww[4] = {(1.f - fx) * (1.f - fy), fx * (1.f - fy),
                                 (1.f - fx) * fy,          fx * fy};
            float4 r = make_float4(0.f, 0.f, 0.f, 0.f);
            #pragma unroll
            for (int k = 0; k < 4; ++k) {
                const int xx = x0 + (k & 1), yy = y0 + (k >> 1);
                const bool valid = (xx >= 0) && (xx < WSZ) && (yy >= 0) && (yy < WSZ);
                const int idx = valid ? (yy * 8 + xx) : 0;
                const float wk = valid ? ww[k] : 0.f;
                const float4 a = inv4[swz4(idx, c4)];
                r.x = fmaf(wk, a.x, r.x);
                r.y = fmaf(wk, a.y, r.y);
                r.z = fmaf(wk, a.z, r.z);
                r.w = fmaf(wk, a.w, r.w);
            }
            outv4[swz4(tok, c4)] = r;
        }
    }
    __syncthreads();

    // ---- phase A: q (warps 0-7, gmem xw -> bufA)  ||  v (warps 8-15, bufB -> bufC) ----
    if (wp < 8) gemm8g(g_xw + (size_t)win * P2 * CH, q_w, 128, 0, q_b, 0, bufA, wp, tx);
    else        gemm8s(bufB, kv_w, 256, 128, kv_b, 128, bufC, wp - 8, tx);
    __syncthreads();
    // ---- phase B: k (warps 0-7, bufB in-place) ----
    if (wp < 8) gemm8s(bufB, kv_w, 256, 0, kv_b, 0, bufB, wp, tx);
    __syncthreads();

    // ---- attention: each warp owns 4 query rows ----
    const float scale = 0.17677669529663687f;
    const bool lastRow = (wi == W1G - 1), lastCol = (wj == W1G - 1);
    const int r0 = wp * 4;
    const float4* qv4 = (const float4*)bufA;
    const float4* kv4 = (const float4*)bufB;
    for (int hh = 0; hh < NH; ++hh) {
        float acc[4][2] = {};
        #pragma unroll
        for (int d4 = 0; d4 < HD / 4; ++d4) {
            const float4 kk0 = kv4[swz4(tx,      hh * 8 + d4)];
            const float4 kk1 = kv4[swz4(tx + 32, hh * 8 + d4)];
            #pragma unroll
            for (int r = 0; r < 4; ++r) {
                const float4 qq = qv4[swz4(r0 + r, hh * 8 + d4)];
                acc[r][0] = fmaf(qq.x, kk0.x, acc[r][0]);
                acc[r][0] = fmaf(qq.y, kk0.y, acc[r][0]);
                acc[r][0] = fmaf(qq.z, kk0.z, acc[r][0]);
                acc[r][0] = fmaf(qq.w, kk0.w, acc[r][0]);
                acc[r][1] = fmaf(qq.x, kk1.x, acc[r][1]);
                acc[r][1] = fmaf(qq.y, kk1.y, acc[r][1]);
                acc[r][1] = fmaf(qq.z, kk1.z, acc[r][1]);
                acc[r][1] = fmaf(qq.w, kk1.w, acc[r][1]);
            }
        }
        const float* rb = rpp + hh * 225;
        #pragma unroll
        for (int r = 0; r < 4; ++r) {
            const int i = r0 + r, pi_i = i >> 3, pj_i = i & 7;
            #pragma unroll
            for (int u = 0; u < 2; ++u) {
                const int j = tx + 32 * u, pi_j = j >> 3, pj_j = j & 7;
                const float bias = rb[(pi_i - pi_j + 7) * 15 + (pj_i - pj_j + 7)];
                const bool msk = (lastRow && ((pi_i < 4) != (pi_j < 4)))
                              || (lastCol && ((pj_i < 4) != (pj_j < 4)));
                sSim[i * 64 + j] = msk ? -CUDART_INF_F : fmaf(acc[r][u], scale, bias);
            }
        }
        __syncwarp();
        #pragma unroll
        for (int r = 0; r < 4; ++r) {
            const int i = r0 + r;
            const float a = sSim[i * 64 + tx], bb = sSim[i * 64 + tx + 32];
            float m = fmaxf(a, bb);
            #pragma unroll
            for (int s2 = 16; s2 > 0; s2 >>= 1) m = fmaxf(m, __shfl_xor_sync(0xffffffffu, m, s2));
            const float e0 = __expf(a - m), e1 = __expf(bb - m);
            float s = e0 + e1;
            #pragma unroll
            for (int s2 = 16; s2 > 0; s2 >>= 1) s += __shfl_xor_sync(0xffffffffu, s, s2);
            const float inv = 1.f / s;
            sSim[i * 64 + tx]      = e0 * inv;
            sSim[i * 64 + tx + 32] = e1 * inv;
        }
        __syncwarp();
        // PV: vectorized sim rows (float4 broadcast) + 4 scalar v per block
        float po[4] = {};
        const int chW = hh * HD + tx;
        #pragma unroll 4
        for (int j4 = 0; j4 < 16; ++j4) {
            const int j = j4 * 4;
            const float4 p0 = *(const float4*)(sSim + (r0 + 0) * 64 + j);
            const float4 p1 = *(const float4*)(sSim + (r0 + 1) * 64 + j);
            const float4 p2 = *(const float4*)(sSim + (r0 + 2) * 64 + j);
            const float4 p3 = *(const float4*)(sSim + (r0 + 3) * 64 + j);
            const float v0 = bufC[swz(j + 0, chW)];
            const float v1 = bufC[swz(j + 1, chW)];
            const float v2 = bufC[swz(j + 2, chW)];
            const float v3 = bufC[swz(j + 3, chW)];
            po[0] = fmaf(p0.x, v0, fmaf(p0.y, v1, fmaf(p0.z, v2, fmaf(p0.w, v3, po[0]))));
            po[1] = fmaf(p1.x, v0, fmaf(p1.y, v1, fmaf(p1.z, v2, fmaf(p1.w, v3, po[1]))));
            po[2] = fmaf(p2.x, v0, fmaf(p2.y, v1, fmaf(p2.z, v2, fmaf(p2.w, v3, po[2]))));
            po[3] = fmaf(p3.x, v0, fmaf(p3.y, v1, fmaf(p3.z, v2, fmaf(p3.w, v3, po[3]))));
        }
        __syncwarp();
        #pragma unroll
        for (int r = 0; r < 4; ++r)
            bufA[swz(r0 + r, chW)] = po[r];
        __syncwarp();
    }
    __syncthreads();

    // ---- o projection (warps 0-7, 8 rows each) + un-shift scatter ----
    if (wp < 8) {
        float acc[8][4] = {};
        const int rr0 = wp * 8;
        const float* wbase = o_w + tx * 4;
        const float4* inv4 = (const float4*)bufA;
        #pragma unroll 2
        for (int c4 = 0; c4 < 32; ++c4) {
            const int ci = c4 * 4;
            const float4 w0 = __ldg((const float4*)(wbase + (ci + 0) * 128));
            const float4 w1 = __ldg((const float4*)(wbase + (ci + 1) * 128));
            const float4 w2 = __ldg((const float4*)(wbase + (ci + 2) * 128));
            const float4 w3 = __ldg((const float4*)(wbase + (ci + 3) * 128));
            #pragma unroll
            for (int r = 0; r < 8; ++r) {
                const float4 a = inv4[swz4(rr0 + r, c4)];
                GEMM8_FMAS(a)
            }
        }
        const float4 bv = *(const float4*)(o_b + tx * 4);
        #pragma unroll
        for (int r = 0; r < 8; ++r) {
            const int tok = rr0 + r, pi = tok >> 3, pj = tok & 7;
            const int rr = (wi * 8 + pi + SHIFT) & 255;
            const int cc = (wj * 8 + pj + SHIFT) & 255;
            float4 o;
            o.x = acc[r][0] + bv.x; o.y = acc[r][1] + bv.y;
            o.z = acc[r][2] + bv.z; o.w = acc[r][3] + bv.w;
            *(float4*)(out + (size_t)((((b << 8) + rr) << 8) + cc) * CH + tx * 4) = o;
        }
    }
}

extern "C" void kernel_launch(void* const* d_in, const int* in_sizes, int n_in,
                              void* d_out, int out_size)
{
    const float* x    = (const float*)d_in[0];
    const float* rpp  = (const float*)d_in[1];
    const float* wi_w = (const float*)d_in[2];
    const float* wi_b = (const float*)d_in[3];
    const float* w1_w = (const float*)d_in[4];
    const float* w1_b = (const float*)d_in[5];
    const float* w2_w = (const float*)d_in[6];
    const float* w2_b = (const float*)d_in[7];
    const float* q_w  = (const float*)d_in[8];
    const float* q_b  = (const float*)d_in[9];
    const float* kv_w = (const float*)d_in[10];
    const float* kv_b = (const float*)d_in[11];
    const float* o_w  = (const float*)d_in[12];
    const float* o_b  = (const float*)d_in[13];
    float* out = (float*)d_out;

    const size_t smem2 = (size_t)(3 * 8192 + 4096) * sizeof(float);
    cudaFuncSetAttribute(k_main, cudaFuncAttributeMaxDynamicSharedMemorySize, (int)smem2);

    k_prep<<<NWIN, 256>>>(x, wi_w, wi_b, w1_w, w1_b, w2_w, w2_b);
    k_main<<<NWIN, NTHR, smem2>>>(rpp, q_w, q_b, kv_w, kv_b, o_w, o_b, out);
}

// round 10
// speedup vs baseline: 1.1625x; 1.1625x over previous
#include <cuda_runtime.h>
#include <math_constants.h>

#define WSZ    8
#define P2     64
#define CH     128
#define W1G    32
#define NWPB   1024
#define BATCH  8
#define NWIN   (BATCH*NWPB)
#define HD     32
#define NH     4
#define SHIFT  4
#define PSTR   132
#define NTHR   512

__device__ __forceinline__ int swz4(int tok, int c4) { return tok * 32 + (c4 ^ (tok & 7)); }
__device__ __forceinline__ int swz(int tok, int ch) {
    return tok * 128 + ((((ch >> 2) ^ (tok & 7))) << 2) + (ch & 3);
}

// ---------------- scratch ----------------
__device__ float g_xw [(size_t)NWIN * P2 * CH];
__device__ float g_off[NWIN * P2 * 2];
__device__ float g_oi [NWIN * 2];

// ---------------- kernel 1 ----------------
__global__ __launch_bounds__(256)
void k_prep(const float* __restrict__ x,
            const float* __restrict__ wi_w, const float* __restrict__ wi_b,
            const float* __restrict__ w1_w, const float* __restrict__ w1_b,
            const float* __restrict__ w2_w, const float* __restrict__ w2_b)
{
    __shared__ float sT[P2 * PSTR];
    __shared__ float sT1[P2 * 2];

    const int win = blockIdx.x;
    const int b   = win >> 10;
    const int wr  = win & 1023;
    const int wi  = wr >> 5;
    const int wj  = wr & 31;
    const int tid = threadIdx.x;

    float4* gx4 = (float4*)(g_xw + (size_t)win * P2 * CH);

    for (int i4 = tid; i4 < P2 * CH / 4; i4 += 256) {
        const int tok = i4 >> 5, c4 = i4 & 31;
        const int pi = tok >> 3, pj = tok & 7;
        const int r = (wi * 8 + pi + SHIFT) & 255;
        const int c = (wj * 8 + pj + SHIFT) & 255;
        const float4 v = *(const float4*)(x + (size_t)((((b << 8) + r) << 8) + c) * CH + c4 * 4);
        *(float4*)(sT + tok * PSTR + c4 * 4) = v;
        gx4[i4] = v;
    }
    __syncthreads();

    {
        const int kind = tid >> 7;
        const int rem  = tid & 127;
        const int tok  = rem >> 1;
        const int d    = rem & 1;
        const float* w = kind ? w1_w : wi_w;
        float acc = 0.f;
        #pragma unroll 8
        for (int ch = 0; ch < 128; ++ch)
            acc = fmaf(sT[tok * PSTR + ch], w[ch * 2 + d], acc);
        if (kind) sT1[tok * 2 + d] = acc + w1_b[d];
        else      g_off[win * 128 + tok * 2 + d] = acc + wi_b[d];
    }
    __syncthreads();

    if (tid < 2) {
        float acc = w2_b[tid];
        for (int f = 0; f < 128; ++f)
            acc = fmaf(sT1[f], w2_w[f * 2 + tid], acc);
        g_oi[win * 2 + tid] = acc;
    }
}

#define GEMM2_FMAS(a)                                     \
    acc[r][0] = fmaf(a.x, w0.x, acc[r][0]);               \
    acc[r][1] = fmaf(a.x, w0.y, acc[r][1]);               \
    acc[r][0] = fmaf(a.y, w1.x, acc[r][0]);               \
    acc[r][1] = fmaf(a.y, w1.y, acc[r][1]);               \
    acc[r][0] = fmaf(a.z, w2.x, acc[r][0]);               \
    acc[r][1] = fmaf(a.z, w2.y, acc[r][1]);               \
    acc[r][0] = fmaf(a.w, w3.x, acc[r][0]);               \
    acc[r][1] = fmaf(a.w, w3.y, acc[r][1]);

// 64x128 GEMM, 16 warps: warp pair (g = wp>>1 rows g*8..+7, hs = wp&1 col half).
// Lane owns 2 cols (hs*64 + 2tx). acc[8][2] = 16 regs, no spill.
__device__ __forceinline__
void gemm16_s(const float* __restrict__ in_s, const float* __restrict__ w,
              int wstride, int woff, const float* __restrict__ bias, int boff,
              float* __restrict__ out_s, int wp, int tx)
{
    float acc[8][2] = {};
    const int g = wp >> 1, hs = wp & 1;
    const int r0 = g * 8;
    const int co = hs * 64 + tx * 2;
    const float* wbase = w + woff + co;
    const float4* inv4 = (const float4*)in_s;
    #pragma unroll 4
    for (int c4 = 0; c4 < 32; ++c4) {
        const int ci = c4 * 4;
        const float2 w0 = __ldg((const float2*)(wbase + (size_t)(ci + 0) * wstride));
        const float2 w1 = __ldg((const float2*)(wbase + (size_t)(ci + 1) * wstride));
        const float2 w2 = __ldg((const float2*)(wbase + (size_t)(ci + 2) * wstride));
        const float2 w3 = __ldg((const float2*)(wbase + (size_t)(ci + 3) * wstride));
        #pragma unroll
        for (int r = 0; r < 8; ++r) {
            const float4 a = inv4[swz4(r0 + r, c4)];
            GEMM2_FMAS(a)
        }
    }
    const float2 bv = *(const float2*)(bias + boff + co);
    #pragma unroll
    for (int r = 0; r < 8; ++r) {
        float2 o;
        o.x = acc[r][0] + bv.x; o.y = acc[r][1] + bv.y;
        *(float2*)(out_s + swz(r0 + r, co)) = o;
    }
}

// same, A streamed from gmem (linear [tok][ch], broadcast __ldg)
__device__ __forceinline__
void gemm16_g(const float* __restrict__ in_g, const float* __restrict__ w,
              int wstride, int woff, const float* __restrict__ bias, int boff,
              float* __restrict__ out_s, int wp, int tx)
{
    float acc[8][2] = {};
    const int g = wp >> 1, hs = wp & 1;
    const int r0 = g * 8;
    const int co = hs * 64 + tx * 2;
    const float* wbase = w + woff + co;
    #pragma unroll 4
    for (int c4 = 0; c4 < 32; ++c4) {
        const int ci = c4 * 4;
        const float2 w0 = __ldg((const float2*)(wbase + (size_t)(ci + 0) * wstride));
        const float2 w1 = __ldg((const float2*)(wbase + (size_t)(ci + 1) * wstride));
        const float2 w2 = __ldg((const float2*)(wbase + (size_t)(ci + 2) * wstride));
        const float2 w3 = __ldg((const float2*)(wbase + (size_t)(ci + 3) * wstride));
        #pragma unroll
        for (int r = 0; r < 8; ++r) {
            const float4 a = __ldg((const float4*)(in_g + (r0 + r) * CH + ci));
            GEMM2_FMAS(a)
        }
    }
    const float2 bv = *(const float2*)(bias + boff + co);
    #pragma unroll
    for (int r = 0; r < 8; ++r) {
        float2 o;
        o.x = acc[r][0] + bv.x; o.y = acc[r][1] + bv.y;
        *(float2*)(out_s + swz(r0 + r, co)) = o;
    }
}

// in-place variant: block-wide barrier between mainloop (reads buf) and
// epilogue (writes buf) — race-free by construction.
__device__ __forceinline__
void gemm16_inplace(float* __restrict__ buf, const float* __restrict__ w,
                    int wstride, int woff, const float* __restrict__ bias, int boff,
                    int wp, int tx)
{
    float acc[8][2] = {};
    const int g = wp >> 1, hs = wp & 1;
    const int r0 = g * 8;
    const int co = hs * 64 + tx * 2;
    const float* wbase = w + woff + co;
    const float4* inv4 = (const float4*)buf;
    #pragma unroll 4
    for (int c4 = 0; c4 < 32; ++c4) {
        const int ci = c4 * 4;
        const float2 w0 = __ldg((const float2*)(wbase + (size_t)(ci + 0) * wstride));
        const float2 w1 = __ldg((const float2*)(wbase + (size_t)(ci + 1) * wstride));
        const float2 w2 = __ldg((const float2*)(wbase + (size_t)(ci + 2) * wstride));
        const float2 w3 = __ldg((const float2*)(wbase + (size_t)(ci + 3) * wstride));
        #pragma unroll
        for (int r = 0; r < 8; ++r) {
            const float4 a = inv4[swz4(r0 + r, c4)];
            GEMM2_FMAS(a)
        }
    }
    __syncthreads();   // ALL reads of buf complete before any write below
    const float2 bv = *(const float2*)(bias + boff + co);
    #pragma unroll
    for (int r = 0; r < 8; ++r) {
        float2 o;
        o.x = acc[r][0] + bv.x; o.y = acc[r][1] + bv.y;
        *(float2*)(buf + swz(r0 + r, co)) = o;
    }
}

// ---------------- kernel 2 ----------------
__global__ __launch_bounds__(NTHR, 2)
void k_main(const float* __restrict__ rpp,
            const float* __restrict__ q_w,  const float* __restrict__ q_b,
            const float* __restrict__ kv_w, const float* __restrict__ kv_b,
            const float* __restrict__ o_w,  const float* __restrict__ o_b,
            float* __restrict__ out)
{
    extern __shared__ float sm[];
    float* bufA = sm;            // q -> attn-out
    float* bufB = bufA + 8192;   // xd2 -> v (in-place, barrier-protected)
    float* bufC = bufB + 8192;   // xd -> k
    float* sSim = bufC + 8192;   // 64x64

    const int win = blockIdx.x;
    const int b   = win >> 10;
    const int wr  = win & 1023;
    const int wi  = wr >> 5;
    const int wj  = wr & 31;
    const int tid = threadIdx.x;
    const int wp  = tid >> 5, tx = tid & 31;

    // ---- inter-window bilinear blend -> bufC (xd) ----
    {
        const float ox = __ldg(g_oi + win * 2 + 0), oy = __ldg(g_oi + win * 2 + 1);
        const float gxp = (float)wj + ox, gyp = (float)wi + oy;
        const float x0f = floorf(gxp), y0f = floorf(gyp);
        const float fx = gxp - x0f, fy = gyp - y0f;
        const int x0 = (int)x0f, y0 = (int)y0f;
        const float wgt[4] = {(1.f - fx) * (1.f - fy), fx * (1.f - fy),
                              (1.f - fx) * fy,          fx * fy};
        const float4* nb[4];
        float nww[4];
        #pragma unroll
        for (int k = 0; k < 4; ++k) {
            const int xx = x0 + (k & 1), yy = y0 + (k >> 1);
            const bool valid = (xx >= 0) && (xx < W1G) && (yy >= 0) && (yy < W1G);
            nb[k]  = (const float4*)(valid ? (g_xw + (size_t)((b << 10) + (yy << 5) + xx) * P2 * CH)
                                           : g_xw);
            nww[k] = valid ? wgt[k] : 0.f;
        }
        float4* outv4 = (float4*)bufC;
        for (int i4 = tid; i4 < 2048; i4 += NTHR) {
            const float4 v0 = __ldg(nb[0] + i4), v1 = __ldg(nb[1] + i4);
            const float4 v2 = __ldg(nb[2] + i4), v3 = __ldg(nb[3] + i4);
            float4 r;
            r.x = nww[0]*v0.x + nww[1]*v1.x + nww[2]*v2.x + nww[3]*v3.x;
            r.y = nww[0]*v0.y + nww[1]*v1.y + nww[2]*v2.y + nww[3]*v3.y;
            r.z = nww[0]*v0.z + nww[1]*v1.z + nww[2]*v2.z + nww[3]*v3.z;
            r.w = nww[0]*v0.w + nww[1]*v1.w + nww[2]*v2.w + nww[3]*v3.w;
            outv4[swz4(i4 >> 5, i4 & 31)] = r;
        }
    }
    __syncthreads();

    // ---- intra-window gather bufC -> bufB (xd2) ----
    {
        const float4* inv4 = (const float4*)bufC;
        float4* outv4 = (float4*)bufB;
        #pragma unroll
        for (int it = 0; it < 4; ++it) {
            const int i4 = tid + it * NTHR;
            const int tok = i4 >> 5, c4 = i4 & 31;
            const int pi = tok >> 3, pj = tok & 7;
            const float o0 = __ldg(g_off + win * 128 + tok * 2);
            const float o1 = __ldg(g_off + win * 128 + tok * 2 + 1);
            const float gx2 = (float)pj + o0, gy2 = (float)pi + o1;
            const float xf = floorf(gx2), yf = floorf(gy2);
            const float fx = gx2 - xf, fy = gy2 - yf;
            const int x0 = (int)xf, y0 = (int)yf;
            const float ww[4] = {(1.f - fx) * (1.f - fy), fx * (1.f - fy),
                                 (1.f - fx) * fy,          fx * fy};
            float4 r = make_float4(0.f, 0.f, 0.f, 0.f);
            #pragma unroll
            for (int k = 0; k < 4; ++k) {
                const int xx = x0 + (k & 1), yy = y0 + (k >> 1);
                const bool valid = (xx >= 0) && (xx < WSZ) && (yy >= 0) && (yy < WSZ);
                const int idx = valid ? (yy * 8 + xx) : 0;
                const float wk = valid ? ww[k] : 0.f;
                const float4 a = inv4[swz4(idx, c4)];
                r.x = fmaf(wk, a.x, r.x);
                r.y = fmaf(wk, a.y, r.y);
                r.z = fmaf(wk, a.z, r.z);
                r.w = fmaf(wk, a.w, r.w);
            }
            outv4[swz4(tok, c4)] = r;
        }
    }
    __syncthreads();

    // ---- GEMMs (16 warps each, acc[8][2]) ----
    // k: bufB(xd2) -> bufC (xd dead) — NOT in-place
    gemm16_s(bufB, kv_w, 256, 0, kv_b, 0, bufC, wp, tx);
    // q: gmem xw -> bufA
    gemm16_g(g_xw + (size_t)win * P2 * CH, q_w, 128, 0, q_b, 0, bufA, wp, tx);
    // v: bufB -> bufB, barrier between reads and writes inside
    gemm16_inplace(bufB, kv_w, 256, 128, kv_b, 128, wp, tx);
    __syncthreads();

    // ---- attention: each warp owns 4 query rows. K = bufC, V = bufB ----
    const float scale = 0.17677669529663687f;
    const bool lastRow = (wi == W1G - 1), lastCol = (wj == W1G - 1);
    const int r0 = wp * 4;
    const float4* qv4 = (const float4*)bufA;
    const float4* kv4 = (const float4*)bufC;
    for (int hh = 0; hh < NH; ++hh) {
        float acc[4][2] = {};
        #pragma unroll
        for (int d4 = 0; d4 < HD / 4; ++d4) {
            const float4 kk0 = kv4[swz4(tx,      hh * 8 + d4)];
            const float4 kk1 = kv4[swz4(tx + 32, hh * 8 + d4)];
            #pragma unroll
            for (int r = 0; r < 4; ++r) {
                const float4 qq = qv4[swz4(r0 + r, hh * 8 + d4)];
                acc[r][0] = fmaf(qq.x, kk0.x, acc[r][0]);
                acc[r][0] = fmaf(qq.y, kk0.y, acc[r][0]);
                acc[r][0] = fmaf(qq.z, kk0.z, acc[r][0]);
                acc[r][0] = fmaf(qq.w, kk0.w, acc[r][0]);
                acc[r][1] = fmaf(qq.x, kk1.x, acc[r][1]);
                acc[r][1] = fmaf(qq.y, kk1.y, acc[r][1]);
                acc[r][1] = fmaf(qq.z, kk1.z, acc[r][1]);
                acc[r][1] = fmaf(qq.w, kk1.w, acc[r][1]);
            }
        }
        const float* rb = rpp + hh * 225;
        #pragma unroll
        for (int r = 0; r < 4; ++r) {
            const int i = r0 + r, pi_i = i >> 3, pj_i = i & 7;
            #pragma unroll
            for (int u = 0; u < 2; ++u) {
                const int j = tx + 32 * u, pi_j = j >> 3, pj_j = j & 7;
                const float bias = rb[(pi_i - pi_j + 7) * 15 + (pj_i - pj_j + 7)];
                const bool msk = (lastRow && ((pi_i < 4) != (pi_j < 4)))
                              || (lastCol && ((pj_i < 4) != (pj_j < 4)));
                sSim[i * 64 + j] = msk ? -CUDART_INF_F : fmaf(acc[r][u], scale, bias);
            }
        }
        __syncwarp();
        #pragma unroll
        for (int r = 0; r < 4; ++r) {
            const int i = r0 + r;
            const float a = sSim[i * 64 + tx], bb = sSim[i * 64 + tx + 32];
            float m = fmaxf(a, bb);
            #pragma unroll
            for (int s2 = 16; s2 > 0; s2 >>= 1) m = fmaxf(m, __shfl_xor_sync(0xffffffffu, m, s2));
            const float e0 = __expf(a - m), e1 = __expf(bb - m);
            float s = e0 + e1;
            #pragma unroll
            for (int s2 = 16; s2 > 0; s2 >>= 1) s += __shfl_xor_sync(0xffffffffu, s, s2);
            const float inv = 1.f / s;
            sSim[i * 64 + tx]      = e0 * inv;
            sSim[i * 64 + tx + 32] = e1 * inv;
        }
        __syncwarp();
        // PV vectorized: float4 sim rows (broadcast) + 4 scalar v per block
        float po[4] = {};
        const int chW = hh * HD + tx;
        #pragma unroll 4
        for (int j4 = 0; j4 < 16; ++j4) {
            const int j = j4 * 4;
            const float4 p0 = *(const float4*)(sSim + (r0 + 0) * 64 + j);
            const float4 p1 = *(const float4*)(sSim + (r0 + 1) * 64 + j);
            const float4 p2 = *(const float4*)(sSim + (r0 + 2) * 64 + j);
            const float4 p3 = *(const float4*)(sSim + (r0 + 3) * 64 + j);
            const float v0 = bufB[swz(j + 0, chW)];
            const float v1 = bufB[swz(j + 1, chW)];
            const float v2 = bufB[swz(j + 2, chW)];
            const float v3 = bufB[swz(j + 3, chW)];
            po[0] = fmaf(p0.x, v0, fmaf(p0.y, v1, fmaf(p0.z, v2, fmaf(p0.w, v3, po[0]))));
            po[1] = fmaf(p1.x, v0, fmaf(p1.y, v1, fmaf(p1.z, v2, fmaf(p1.w, v3, po[1]))));
            po[2] = fmaf(p2.x, v0, fmaf(p2.y, v1, fmaf(p2.z, v2, fmaf(p2.w, v3, po[2]))));
            po[3] = fmaf(p3.x, v0, fmaf(p3.y, v1, fmaf(p3.z, v2, fmaf(p3.w, v3, po[3]))));
        }
        __syncwarp();
        #pragma unroll
        for (int r = 0; r < 4; ++r)
            bufA[swz(r0 + r, chW)] = po[r];
        __syncwarp();
    }
    __syncthreads();

    // ---- o projection (16 warps, acc[8][2]; reads bufA, writes gmem) ----
    {
        float acc[8][2] = {};
        const int g = wp >> 1, hs = wp & 1;
        const int rr0 = g * 8;
        const int co = hs * 64 + tx * 2;
        const float* wbase = o_w + co;
        const float4* inv4 = (const float4*)bufA;
        #pragma unroll 4
        for (int c4 = 0; c4 < 32; ++c4) {
            const int ci = c4 * 4;
            const float2 w0 = __ldg((const float2*)(wbase + (ci + 0) * 128));
            const float2 w1 = __ldg((const float2*)(wbase + (ci + 1) * 128));
            const float2 w2 = __ldg((const float2*)(wbase + (ci + 2) * 128));
            const float2 w3 = __ldg((const float2*)(wbase + (ci + 3) * 128));
            #pragma unroll
            for (int r = 0; r < 8; ++r) {
                const float4 a = inv4[swz4(rr0 + r, c4)];
                GEMM2_FMAS(a)
            }
        }
        const float2 bv = *(const float2*)(o_b + co);
        #pragma unroll
        for (int r = 0; r < 8; ++r) {
            const int tok = rr0 + r, pi = tok >> 3, pj = tok & 7;
            const int rr = (wi * 8 + pi + SHIFT) & 255;
            const int cc = (wj * 8 + pj + SHIFT) & 255;
            float2 o;
            o.x = acc[r][0] + bv.x; o.y = acc[r][1] + bv.y;
            *(float2*)(out + (size_t)((((b << 8) + rr) << 8) + cc) * CH + co) = o;
        }
    }
}

extern "C" void kernel_launch(void* const* d_in, const int* in_sizes, int n_in,
                              void* d_out, int out_size)
{
    const float* x    = (const float*)d_in[0];
    const float* rpp  = (const float*)d_in[1];
    const float* wi_w = (const float*)d_in[2];
    const float* wi_b = (const float*)d_in[3];
    const float* w1_w = (const float*)d_in[4];
    const float* w1_b = (const float*)d_in[5];
    const float* w2_w = (const float*)d_in[6];
    const float* w2_b = (const float*)d_in[7];
    const float* q_w  = (const float*)d_in[8];
    const float* q_b  = (const float*)d_in[9];
    const float* kv_w = (const float*)d_in[10];
    const float* kv_b = (const float*)d_in[11];
    const float* o_w  = (const float*)d_in[12];
    const float* o_b  = (const float*)d_in[13];
    float* out = (float*)d_out;

    const size_t smem2 = (size_t)(3 * 8192 + 4096) * sizeof(float);
    cudaFuncSetAttribute(k_main, cudaFuncAttributeMaxDynamicSharedMemorySize, (int)smem2);

    k_prep<<<NWIN, 256>>>(x, wi_w, wi_b, w1_w, w1_b, w2_w, w2_b);
    k_main<<<NWIN, NTHR, smem2>>>(rpp, q_w, q_b, kv_w, kv_b, o_w, o_b, out);
}

// round 11
// speedup vs baseline: 1.9511x; 1.6784x over previous
#include <cuda_runtime.h>
#include <math_constants.h>

#define WSZ    8
#define P2     64
#define CH     128
#define W1G    32
#define NWPB   1024
#define BATCH  8
#define NWIN   (BATCH*NWPB)
#define HD     32
#define NH     4
#define SHIFT  4
#define PSTR   132
#define NTHR   512

__device__ __forceinline__ int swz4(int tok, int c4) { return tok * 32 + (c4 ^ (tok & 7)); }
__device__ __forceinline__ int swz(int tok, int ch) {
    return tok * 128 + ((((ch >> 2) ^ (tok & 7))) << 2) + (ch & 3);
}

// bf16 split helpers: hi = truncate mantissa to bf16, lo = round(x - hi)
__device__ __forceinline__ float trunc_hi(float x) {
    return __uint_as_float(__float_as_uint(x) & 0xffff0000u);
}
__device__ __forceinline__ unsigned prmt_hi(float a, float b) {   // lo half = bf16_trunc(a)
    unsigned r;
    asm("prmt.b32 %0, %1, %2, 0x7632;" : "=r"(r)
        : "r"(__float_as_uint(a)), "r"(__float_as_uint(b)));
    return r;
}
__device__ __forceinline__ unsigned pack_rn(float a, float b) {   // lo half = bf16_rn(a)
    unsigned r;
    asm("cvt.rn.bf16x2.f32 %0, %1, %2;" : "=r"(r) : "f"(b), "f"(a));
    return r;
}
__device__ __forceinline__ void mma_bf16(float c[4], unsigned a0, unsigned a1,
                                         unsigned a2, unsigned a3,
                                         unsigned b0, unsigned b1) {
    asm volatile(
        "mma.sync.aligned.m16n8k16.row.col.f32.bf16.bf16.f32 "
        "{%0,%1,%2,%3}, {%4,%5,%6,%7}, {%8,%9}, {%0,%1,%2,%3};\n"
        : "+f"(c[0]), "+f"(c[1]), "+f"(c[2]), "+f"(c[3])
        : "r"(a0), "r"(a1), "r"(a2), "r"(a3), "r"(b0), "r"(b1));
}

// ---------------- scratch ----------------
__device__ float g_xw [(size_t)NWIN * P2 * CH];
__device__ float g_off[NWIN * P2 * 2];
__device__ float g_oi [NWIN * 2];
// weight fragments (bf16 hi/lo), fragment-order: idx = (n8*8+ks)*32 + lane
__device__ uint2 g_qfh[4096], g_qfl[4096];
__device__ uint2 g_kfh[4096], g_kfl[4096];
__device__ uint2 g_vfh[4096], g_vfl[4096];
__device__ uint2 g_ofh[4096], g_ofl[4096];

// ---------------- kernel 0: weight fragment prep (tiny) ----------------
__global__ __launch_bounds__(256)
void k_wfrag(const float* __restrict__ q_w, const float* __restrict__ kv_w,
             const float* __restrict__ o_w)
{
    const int i = blockIdx.x * 256 + threadIdx.x;    // 0..4095
    const int lane = i & 31, ks = (i >> 5) & 7, n8 = i >> 8;
    const int n  = n8 * 8 + (lane >> 2);
    const int kb = ks * 16 + (lane & 3) * 2;

    #define DO_FRAG(w, S, O, fh, fl) {                                        \
        const float v00 = w[(size_t)(kb    ) * S + O + n];                    \
        const float v01 = w[(size_t)(kb + 1) * S + O + n];                    \
        const float v10 = w[(size_t)(kb + 8) * S + O + n];                    \
        const float v11 = w[(size_t)(kb + 9) * S + O + n];                    \
        fh[i] = make_uint2(prmt_hi(v00, v01), prmt_hi(v10, v11));             \
        fl[i] = make_uint2(pack_rn(v00 - trunc_hi(v00), v01 - trunc_hi(v01)), \
                           pack_rn(v10 - trunc_hi(v10), v11 - trunc_hi(v11)));\
    }
    DO_FRAG(q_w, 128, 0,   g_qfh, g_qfl)
    DO_FRAG(kv_w, 256, 0,   g_kfh, g_kfl)
    DO_FRAG(kv_w, 256, 128, g_vfh, g_vfl)
    DO_FRAG(o_w, 128, 0,   g_ofh, g_ofl)
    #undef DO_FRAG
}

// ---------------- kernel 1: window gather + offset MLPs ----------------
__global__ __launch_bounds__(256)
void k_prep(const float* __restrict__ x,
            const float* __restrict__ wi_w, const float* __restrict__ wi_b,
            const float* __restrict__ w1_w, const float* __restrict__ w1_b,
            const float* __restrict__ w2_w, const float* __restrict__ w2_b)
{
    __shared__ float sT[P2 * PSTR];
    __shared__ float sT1[P2 * 2];

    const int win = blockIdx.x;
    const int b   = win >> 10;
    const int wr  = win & 1023;
    const int wi  = wr >> 5;
    const int wj  = wr & 31;
    const int tid = threadIdx.x;

    float4* gx4 = (float4*)(g_xw + (size_t)win * P2 * CH);

    for (int i4 = tid; i4 < P2 * CH / 4; i4 += 256) {
        const int tok = i4 >> 5, c4 = i4 & 31;
        const int pi = tok >> 3, pj = tok & 7;
        const int r = (wi * 8 + pi + SHIFT) & 255;
        const int c = (wj * 8 + pj + SHIFT) & 255;
        const float4 v = *(const float4*)(x + (size_t)((((b << 8) + r) << 8) + c) * CH + c4 * 4);
        *(float4*)(sT + tok * PSTR + c4 * 4) = v;
        gx4[i4] = v;
    }
    __syncthreads();

    {
        const int kind = tid >> 7;
        const int rem  = tid & 127;
        const int tok  = rem >> 1;
        const int d    = rem & 1;
        const float* w = kind ? w1_w : wi_w;
        float acc = 0.f;
        #pragma unroll 8
        for (int ch = 0; ch < 128; ++ch)
            acc = fmaf(sT[tok * PSTR + ch], w[ch * 2 + d], acc);
        if (kind) sT1[tok * 2 + d] = acc + w1_b[d];
        else      g_off[win * 128 + tok * 2 + d] = acc + wi_b[d];
    }
    __syncthreads();

    if (tid < 2) {
        float acc = w2_b[tid];
        for (int f = 0; f < 128; ++f)
            acc = fmaf(sT1[f], w2_w[f * 2 + tid], acc);
        g_oi[win * 2 + tid] = acc;
    }
}

// ---- bf16x3 MMA mainloops: warp wp = rg(rows rg*16..+15) x cg(cols cg*32..+31) ----
#define MMA_KSTEP(LD0, LD1, LD2, LD3)                                          \
    const float2 L0 = LD0, L1 = LD1, L2 = LD2, L3 = LD3;                       \
    const unsigned ah0 = prmt_hi(L0.x, L0.y), ah1 = prmt_hi(L1.x, L1.y);       \
    const unsigned ah2 = prmt_hi(L2.x, L2.y), ah3 = prmt_hi(L3.x, L3.y);       \
    const unsigned al0 = pack_rn(L0.x - trunc_hi(L0.x), L0.y - trunc_hi(L0.y));\
    const unsigned al1 = pack_rn(L1.x - trunc_hi(L1.x), L1.y - trunc_hi(L1.y));\
    const unsigned al2 = pack_rn(L2.x - trunc_hi(L2.x), L2.y - trunc_hi(L2.y));\
    const unsigned al3 = pack_rn(L3.x - trunc_hi(L3.x), L3.y - trunc_hi(L3.y));\
    _Pragma("unroll")                                                          \
    for (int nt = 0; nt < 4; ++nt) {                                           \
        const int fi = ((cg * 4 + nt) * 8 + ks) * 32 + lane;                   \
        const uint2 bh = __ldg(wh + fi);                                       \
        const uint2 bl = __ldg(wl + fi);                                       \
        mma_bf16(c[nt], ah0, ah1, ah2, ah3, bh.x, bh.y);                       \
        mma_bf16(c[nt], al0, al1, al2, al3, bh.x, bh.y);                       \
        mma_bf16(c[nt], ah0, ah1, ah2, ah3, bl.x, bl.y);                       \
    }

__device__ __forceinline__
void mma_main_smem(const float* __restrict__ A, const uint2* __restrict__ wh,
                   const uint2* __restrict__ wl, int wp, int lane, float c[4][4])
{
    const int rg = wp >> 2, cg = wp & 3;
    const int r = rg * 16 + (lane >> 2);
    const int q2 = (lane & 3) * 2;
    #pragma unroll
    for (int ks = 0; ks < 8; ++ks) {
        const int k0 = ks * 16;
        MMA_KSTEP(*(const float2*)(A + swz(r,     k0 + q2)),
                  *(const float2*)(A + swz(r + 8, k0 + q2)),
                  *(const float2*)(A + swz(r,     k0 + 8 + q2)),
                  *(const float2*)(A + swz(r + 8, k0 + 8 + q2)))
    }
}

__device__ __forceinline__
void mma_main_gmem(const float* __restrict__ A, const uint2* __restrict__ wh,
                   const uint2* __restrict__ wl, int wp, int lane, float c[4][4])
{
    const int rg = wp >> 2, cg = wp & 3;
    const int r = rg * 16 + (lane >> 2);
    const int q2 = (lane & 3) * 2;
    #pragma unroll
    for (int ks = 0; ks < 8; ++ks) {
        const int k0 = ks * 16;
        MMA_KSTEP(__ldg((const float2*)(A + (r    ) * CH + k0 + q2)),
                  __ldg((const float2*)(A + (r + 8) * CH + k0 + q2)),
                  __ldg((const float2*)(A + (r    ) * CH + k0 + 8 + q2)),
                  __ldg((const float2*)(A + (r + 8) * CH + k0 + 8 + q2)))
    }
}

__device__ __forceinline__
void mma_epi_smem(float c[4][4], const float* __restrict__ bias, int boff,
                  float* __restrict__ out_s, int wp, int lane)
{
    const int rg = wp >> 2, cg = wp & 3;
    const int r = rg * 16 + (lane >> 2);
    const int q2 = (lane & 3) * 2;
    #pragma unroll
    for (int nt = 0; nt < 4; ++nt) {
        const int col = cg * 32 + nt * 8 + q2;
        const float2 bv = *(const float2*)(bias + boff + col);
        *(float2*)(out_s + swz(r,     col)) = make_float2(c[nt][0] + bv.x, c[nt][1] + bv.y);
        *(float2*)(out_s + swz(r + 8, col)) = make_float2(c[nt][2] + bv.x, c[nt][3] + bv.y);
    }
}

// ---------------- kernel 2 ----------------
__global__ __launch_bounds__(NTHR, 2)
void k_main(const float* __restrict__ rpp,
            const float* __restrict__ q_b, const float* __restrict__ kv_b,
            const float* __restrict__ o_b, float* __restrict__ out)
{
    extern __shared__ float sm[];
    float* bufA = sm;            // q -> attn-out
    float* bufB = bufA + 8192;   // xd2 -> v (in-place, barrier-protected)
    float* bufC = bufB + 8192;   // xd -> k
    float* sSim = bufC + 8192;   // 64x64

    const int win = blockIdx.x;
    const int b   = win >> 10;
    const int wr  = win & 1023;
    const int wi  = wr >> 5;
    const int wj  = wr & 31;
    const int tid = threadIdx.x;
    const int wp  = tid >> 5, tx = tid & 31;

    // ---- inter-window bilinear blend -> bufC (xd) ----
    {
        const float ox = __ldg(g_oi + win * 2 + 0), oy = __ldg(g_oi + win * 2 + 1);
        const float gxp = (float)wj + ox, gyp = (float)wi + oy;
        const float x0f = floorf(gxp), y0f = floorf(gyp);
        const float fx = gxp - x0f, fy = gyp - y0f;
        const int x0 = (int)x0f, y0 = (int)y0f;
        const float wgt[4] = {(1.f - fx) * (1.f - fy), fx * (1.f - fy),
                              (1.f - fx) * fy,          fx * fy};
        const float4* nb[4];
        float nww[4];
        #pragma unroll
        for (int k = 0; k < 4; ++k) {
            const int xx = x0 + (k & 1), yy = y0 + (k >> 1);
            const bool valid = (xx >= 0) && (xx < W1G) && (yy >= 0) && (yy < W1G);
            nb[k]  = (const float4*)(valid ? (g_xw + (size_t)((b << 10) + (yy << 5) + xx) * P2 * CH)
                                           : g_xw);
            nww[k] = valid ? wgt[k] : 0.f;
        }
        float4* outv4 = (float4*)bufC;
        for (int i4 = tid; i4 < 2048; i4 += NTHR) {
            const float4 v0 = __ldg(nb[0] + i4), v1 = __ldg(nb[1] + i4);
            const float4 v2 = __ldg(nb[2] + i4), v3 = __ldg(nb[3] + i4);
            float4 r;
            r.x = nww[0]*v0.x + nww[1]*v1.x + nww[2]*v2.x + nww[3]*v3.x;
            r.y = nww[0]*v0.y + nww[1]*v1.y + nww[2]*v2.y + nww[3]*v3.y;
            r.z = nww[0]*v0.z + nww[1]*v1.z + nww[2]*v2.z + nww[3]*v3.z;
            r.w = nww[0]*v0.w + nww[1]*v1.w + nww[2]*v2.w + nww[3]*v3.w;
            outv4[swz4(i4 >> 5, i4 & 31)] = r;
        }
    }
    __syncthreads();

    // ---- intra-window gather bufC -> bufB (xd2) ----
    {
        const float4* inv4 = (const float4*)bufC;
        float4* outv4 = (float4*)bufB;
        #pragma unroll
        for (int it = 0; it < 4; ++it) {
            const int i4 = tid + it * NTHR;
            const int tok = i4 >> 5, c4 = i4 & 31;
            const int pi = tok >> 3, pj = tok & 7;
            const float o0 = __ldg(g_off + win * 128 + tok * 2);
            const float o1 = __ldg(g_off + win * 128 + tok * 2 + 1);
            const float gx2 = (float)pj + o0, gy2 = (float)pi + o1;
            const float xf = floorf(gx2), yf = floorf(gy2);
            const float fx = gx2 - xf, fy = gy2 - yf;
            const int x0 = (int)xf, y0 = (int)yf;
            const float ww[4] = {(1.f - fx) * (1.f - fy), fx * (1.f - fy),
                                 (1.f - fx) * fy,          fx * fy};
            float4 r = make_float4(0.f, 0.f, 0.f, 0.f);
            #pragma unroll
            for (int k = 0; k < 4; ++k) {
                const int xx = x0 + (k & 1), yy = y0 + (k >> 1);
                const bool valid = (xx >= 0) && (xx < WSZ) && (yy >= 0) && (yy < WSZ);
                const int idx = valid ? (yy * 8 + xx) : 0;
                const float wk = valid ? ww[k] : 0.f;
                const float4 a = inv4[swz4(idx, c4)];
                r.x = fmaf(wk, a.x, r.x);
                r.y = fmaf(wk, a.y, r.y);
                r.z = fmaf(wk, a.z, r.z);
                r.w = fmaf(wk, a.w, r.w);
            }
            outv4[swz4(tok, c4)] = r;
        }
    }
    __syncthreads();

    // ---- GEMMs on tensor cores (bf16x3) ----
    {   // k: bufB(xd2) -> bufC (xd dead)
        float c[4][4] = {};
        mma_main_smem(bufB, g_kfh, g_kfl, wp, tx, c);
        mma_epi_smem(c, kv_b, 0, bufC, wp, tx);
    }
    {   // q: gmem xw -> bufA
        float c[4][4] = {};
        mma_main_gmem(g_xw + (size_t)win * P2 * CH, g_qfh, g_qfl, wp, tx, c);
        mma_epi_smem(c, q_b, 0, bufA, wp, tx);
    }
    {   // v: bufB -> bufB in-place, block barrier between reads and writes
        float c[4][4] = {};
        mma_main_smem(bufB, g_vfh, g_vfl, wp, tx, c);
        __syncthreads();
        mma_epi_smem(c, kv_b, 128, bufB, wp, tx);
    }
    __syncthreads();

    // ---- attention: each warp owns 4 query rows. Q=bufA, K=bufC, V=bufB ----
    const float scale = 0.17677669529663687f;
    const bool lastRow = (wi == W1G - 1), lastCol = (wj == W1G - 1);
    const int r0 = wp * 4;
    const float4* qv4 = (const float4*)bufA;
    const float4* kv4 = (const float4*)bufC;
    for (int hh = 0; hh < NH; ++hh) {
        float acc[4][2] = {};
        #pragma unroll
        for (int d4 = 0; d4 < HD / 4; ++d4) {
            const float4 kk0 = kv4[swz4(tx,      hh * 8 + d4)];
            const float4 kk1 = kv4[swz4(tx + 32, hh * 8 + d4)];
            #pragma unroll
            for (int r = 0; r < 4; ++r) {
                const float4 qq = qv4[swz4(r0 + r, hh * 8 + d4)];
                acc[r][0] = fmaf(qq.x, kk0.x, acc[r][0]);
                acc[r][0] = fmaf(qq.y, kk0.y, acc[r][0]);
                acc[r][0] = fmaf(qq.z, kk0.z, acc[r][0]);
                acc[r][0] = fmaf(qq.w, kk0.w, acc[r][0]);
                acc[r][1] = fmaf(qq.x, kk1.x, acc[r][1]);
                acc[r][1] = fmaf(qq.y, kk1.y, acc[r][1]);
                acc[r][1] = fmaf(qq.z, kk1.z, acc[r][1]);
                acc[r][1] = fmaf(qq.w, kk1.w, acc[r][1]);
            }
        }
        const float* rb = rpp + hh * 225;
        #pragma unroll
        for (int r = 0; r < 4; ++r) {
            const int i = r0 + r, pi_i = i >> 3, pj_i = i & 7;
            #pragma unroll
            for (int u = 0; u < 2; ++u) {
                const int j = tx + 32 * u, pi_j = j >> 3, pj_j = j & 7;
                const float bias = rb[(pi_i - pi_j + 7) * 15 + (pj_i - pj_j + 7)];
                const bool msk = (lastRow && ((pi_i < 4) != (pi_j < 4)))
                              || (lastCol && ((pj_i < 4) != (pj_j < 4)));
                sSim[i * 64 + j] = msk ? -CUDART_INF_F : fmaf(acc[r][u], scale, bias);
            }
        }
        __syncwarp();
        #pragma unroll
        for (int r = 0; r < 4; ++r) {
            const int i = r0 + r;
            const float a = sSim[i * 64 + tx], bb = sSim[i * 64 + tx + 32];
            float m = fmaxf(a, bb);
            #pragma unroll
            for (int s2 = 16; s2 > 0; s2 >>= 1) m = fmaxf(m, __shfl_xor_sync(0xffffffffu, m, s2));
            const float e0 = __expf(a - m), e1 = __expf(bb - m);
            float s = e0 + e1;
            #pragma unroll
            for (int s2 = 16; s2 > 0; s2 >>= 1) s += __shfl_xor_sync(0xffffffffu, s, s2);
            const float inv = 1.f / s;
            sSim[i * 64 + tx]      = e0 * inv;
            sSim[i * 64 + tx + 32] = e1 * inv;
        }
        __syncwarp();
        float po[4] = {};
        const int chW = hh * HD + tx;
        #pragma unroll 4
        for (int j4 = 0; j4 < 16; ++j4) {
            const int j = j4 * 4;
            const float4 p0 = *(const float4*)(sSim + (r0 + 0) * 64 + j);
            const float4 p1 = *(const float4*)(sSim + (r0 + 1) * 64 + j);
            const float4 p2 = *(const float4*)(sSim + (r0 + 2) * 64 + j);
            const float4 p3 = *(const float4*)(sSim + (r0 + 3) * 64 + j);
            const float v0 = bufB[swz(j + 0, chW)];
            const float v1 = bufB[swz(j + 1, chW)];
            const float v2 = bufB[swz(j + 2, chW)];
            const float v3 = bufB[swz(j + 3, chW)];
            po[0] = fmaf(p0.x, v0, fmaf(p0.y, v1, fmaf(p0.z, v2, fmaf(p0.w, v3, po[0]))));
            po[1] = fmaf(p1.x, v0, fmaf(p1.y, v1, fmaf(p1.z, v2, fmaf(p1.w, v3, po[1]))));
            po[2] = fmaf(p2.x, v0, fmaf(p2.y, v1, fmaf(p2.z, v2, fmaf(p2.w, v3, po[2]))));
            po[3] = fmaf(p3.x, v0, fmaf(p3.y, v1, fmaf(p3.z, v2, fmaf(p3.w, v3, po[3]))));
        }
        __syncwarp();
        #pragma unroll
        for (int r = 0; r < 4; ++r)
            bufA[swz(r0 + r, chW)] = po[r];
        __syncwarp();
    }
    __syncthreads();

    // ---- o projection on tensor cores + un-shift scatter ----
    {
        float c[4][4] = {};
        mma_main_smem(bufA, g_ofh, g_ofl, wp, tx, c);
        const int rg = wp >> 2, cg = wp & 3;
        const int rA = rg * 16 + (tx >> 2);
        const int q2 = (tx & 3) * 2;
        #pragma unroll
        for (int nt = 0; nt < 4; ++nt) {
            const int col = cg * 32 + nt * 8 + q2;
            const float2 bv = *(const float2*)(o_b + col);
            #pragma unroll
            for (int h = 0; h < 2; ++h) {
                const int tok = rA + 8 * h;
                const int pi = tok >> 3, pj = tok & 7;
                const int rr = (wi * 8 + pi + SHIFT) & 255;
                const int cc = (wj * 8 + pj + SHIFT) & 255;
                float2 o;
                o.x = c[nt][2 * h + 0] + bv.x;
                o.y = c[nt][2 * h + 1] + bv.y;
                *(float2*)(out + (size_t)((((b << 8) + rr) << 8) + cc) * CH + col) = o;
            }
        }
    }
}

extern "C" void kernel_launch(void* const* d_in, const int* in_sizes, int n_in,
                              void* d_out, int out_size)
{
    const float* x    = (const float*)d_in[0];
    const float* rpp  = (const float*)d_in[1];
    const float* wi_w = (const float*)d_in[2];
    const float* wi_b = (const float*)d_in[3];
    const float* w1_w = (const float*)d_in[4];
    const float* w1_b = (const float*)d_in[5];
    const float* w2_w = (const float*)d_in[6];
    const float* w2_b = (const float*)d_in[7];
    const float* q_w  = (const float*)d_in[8];
    const float* q_b  = (const float*)d_in[9];
    const float* kv_w = (const float*)d_in[10];
    const float* kv_b = (const float*)d_in[11];
    const float* o_w  = (const float*)d_in[12];
    const float* o_b  = (const float*)d_in[13];
    float* out = (float*)d_out;

    const size_t smem2 = (size_t)(3 * 8192 + 4096) * sizeof(float);
    cudaFuncSetAttribute(k_main, cudaFuncAttributeMaxDynamicSharedMemorySize, (int)smem2);

    k_wfrag<<<16, 256>>>(q_w, kv_w, o_w);
    k_prep<<<NWIN, 256>>>(x, wi_w, wi_b, w1_w, w1_b, w2_w, w2_b);
    k_main<<<NWIN, NTHR, smem2>>>(rpp, q_b, kv_b, o_b, out);
}

// round 12
// speedup vs baseline: 2.1029x; 1.0778x over previous
#include <cuda_runtime.h>
#include <math_constants.h>

#define WSZ    8
#define P2     64
#define CH     128
#define W1G    32
#define NWPB   1024
#define BATCH  8
#define NWIN   (BATCH*NWPB)
#define HD     32
#define NH     4
#define SHIFT  4
#define PSTR   132
#define NTHR   512

__device__ __forceinline__ int swz4(int tok, int c4) { return tok * 32 + (c4 ^ (tok & 7)); }
__device__ __forceinline__ int swz(int tok, int ch) {
    return tok * 128 + ((((ch >> 2) ^ (tok & 7))) << 2) + (ch & 3);
}
// sim buffer swizzle (64x64, float2-safe, <=2-way conflicts for MMA frag loads)
__device__ __forceinline__ int sswz(int i, int j) { return i * 64 + (j ^ ((i & 7) << 3)); }

// bf16 split helpers
__device__ __forceinline__ float trunc_hi(float x) {
    return __uint_as_float(__float_as_uint(x) & 0xffff0000u);
}
__device__ __forceinline__ unsigned prmt_hi(float a, float b) {
    unsigned r;
    asm("prmt.b32 %0, %1, %2, 0x7632;" : "=r"(r)
        : "r"(__float_as_uint(a)), "r"(__float_as_uint(b)));
    return r;
}
__device__ __forceinline__ unsigned pack_rn(float a, float b) {
    unsigned r;
    asm("cvt.rn.bf16x2.f32 %0, %1, %2;" : "=r"(r) : "f"(b), "f"(a));
    return r;
}
__device__ __forceinline__ void split2(float2 f, unsigned& h, unsigned& l) {
    h = prmt_hi(f.x, f.y);
    l = pack_rn(f.x - trunc_hi(f.x), f.y - trunc_hi(f.y));
}
__device__ __forceinline__ void mma_bf16(float c[4], unsigned a0, unsigned a1,
                                         unsigned a2, unsigned a3,
                                         unsigned b0, unsigned b1) {
    asm volatile(
        "mma.sync.aligned.m16n8k16.row.col.f32.bf16.bf16.f32 "
        "{%0,%1,%2,%3}, {%4,%5,%6,%7}, {%8,%9}, {%0,%1,%2,%3};\n"
        : "+f"(c[0]), "+f"(c[1]), "+f"(c[2]), "+f"(c[3])
        : "r"(a0), "r"(a1), "r"(a2), "r"(a3), "r"(b0), "r"(b1));
}

// ---------------- scratch ----------------
__device__ float g_xw [(size_t)NWIN * P2 * CH];
__device__ float g_off[NWIN * P2 * 2];
__device__ float g_oi [NWIN * 2];
__device__ uint2 g_qfh[4096], g_qfl[4096];
__device__ uint2 g_kfh[4096], g_kfl[4096];
__device__ uint2 g_vfh[4096], g_vfl[4096];
__device__ uint2 g_ofh[4096], g_ofl[4096];

// ---------------- kernel 0: weight fragment prep ----------------
__global__ __launch_bounds__(256)
void k_wfrag(const float* __restrict__ q_w, const float* __restrict__ kv_w,
             const float* __restrict__ o_w)
{
    const int i = blockIdx.x * 256 + threadIdx.x;
    const int lane = i & 31, ks = (i >> 5) & 7, n8 = i >> 8;
    const int n  = n8 * 8 + (lane >> 2);
    const int kb = ks * 16 + (lane & 3) * 2;

    #define DO_FRAG(w, S, O, fh, fl) {                                        \
        const float v00 = w[(size_t)(kb    ) * S + O + n];                    \
        const float v01 = w[(size_t)(kb + 1) * S + O + n];                    \
        const float v10 = w[(size_t)(kb + 8) * S + O + n];                    \
        const float v11 = w[(size_t)(kb + 9) * S + O + n];                    \
        fh[i] = make_uint2(prmt_hi(v00, v01), prmt_hi(v10, v11));             \
        fl[i] = make_uint2(pack_rn(v00 - trunc_hi(v00), v01 - trunc_hi(v01)), \
                           pack_rn(v10 - trunc_hi(v10), v11 - trunc_hi(v11)));\
    }
    DO_FRAG(q_w, 128, 0,   g_qfh, g_qfl)
    DO_FRAG(kv_w, 256, 0,   g_kfh, g_kfl)
    DO_FRAG(kv_w, 256, 128, g_vfh, g_vfl)
    DO_FRAG(o_w, 128, 0,   g_ofh, g_ofl)
    #undef DO_FRAG
}

// ---------------- kernel 1: window gather + offset MLPs ----------------
__global__ __launch_bounds__(256)
void k_prep(const float* __restrict__ x,
            const float* __restrict__ wi_w, const float* __restrict__ wi_b,
            const float* __restrict__ w1_w, const float* __restrict__ w1_b,
            const float* __restrict__ w2_w, const float* __restrict__ w2_b)
{
    __shared__ float sT[P2 * PSTR];
    __shared__ float sT1[P2 * 2];

    const int win = blockIdx.x;
    const int b   = win >> 10;
    const int wr  = win & 1023;
    const int wi  = wr >> 5;
    const int wj  = wr & 31;
    const int tid = threadIdx.x;

    float4* gx4 = (float4*)(g_xw + (size_t)win * P2 * CH);

    for (int i4 = tid; i4 < P2 * CH / 4; i4 += 256) {
        const int tok = i4 >> 5, c4 = i4 & 31;
        const int pi = tok >> 3, pj = tok & 7;
        const int r = (wi * 8 + pi + SHIFT) & 255;
        const int c = (wj * 8 + pj + SHIFT) & 255;
        const float4 v = *(const float4*)(x + (size_t)((((b << 8) + r) << 8) + c) * CH + c4 * 4);
        *(float4*)(sT + tok * PSTR + c4 * 4) = v;
        gx4[i4] = v;
    }
    __syncthreads();

    {
        const int kind = tid >> 7;
        const int rem  = tid & 127;
        const int tok  = rem >> 1;
        const int d    = rem & 1;
        const float* w = kind ? w1_w : wi_w;
        float acc = 0.f;
        #pragma unroll 8
        for (int ch = 0; ch < 128; ++ch)
            acc = fmaf(sT[tok * PSTR + ch], w[ch * 2 + d], acc);
        if (kind) sT1[tok * 2 + d] = acc + w1_b[d];
        else      g_off[win * 128 + tok * 2 + d] = acc + wi_b[d];
    }
    __syncthreads();

    if (tid < 2) {
        float acc = w2_b[tid];
        for (int f = 0; f < 128; ++f)
            acc = fmaf(sT1[f], w2_w[f * 2 + tid], acc);
        g_oi[win * 2 + tid] = acc;
    }
}

// ---- bf16x3 MMA mainloops for GEMMs (warp = rg x cg of 16x32 tile) ----
#define MMA_KSTEP(LD0, LD1, LD2, LD3)                                          \
    unsigned ah0, al0, ah1, al1, ah2, al2, ah3, al3;                           \
    split2(LD0, ah0, al0); split2(LD1, ah1, al1);                              \
    split2(LD2, ah2, al2); split2(LD3, ah3, al3);                              \
    _Pragma("unroll")                                                          \
    for (int nt = 0; nt < 4; ++nt) {                                           \
        const int fi = ((cg * 4 + nt) * 8 + ks) * 32 + lane;                   \
        const uint2 bh = __ldg(wh + fi);                                       \
        const uint2 bl = __ldg(wl + fi);                                       \
        mma_bf16(c[nt], ah0, ah1, ah2, ah3, bh.x, bh.y);                       \
        mma_bf16(c[nt], al0, al1, al2, al3, bh.x, bh.y);                       \
        mma_bf16(c[nt], ah0, ah1, ah2, ah3, bl.x, bl.y);                       \
    }

__device__ __forceinline__
void mma_main_smem(const float* __restrict__ A, const uint2* __restrict__ wh,
                   const uint2* __restrict__ wl, int wp, int lane, float c[4][4])
{
    const int rg = wp >> 2, cg = wp & 3;
    const int r = rg * 16 + (lane >> 2);
    const int q2 = (lane & 3) * 2;
    #pragma unroll
    for (int ks = 0; ks < 8; ++ks) {
        const int k0 = ks * 16;
        MMA_KSTEP(*(const float2*)(A + swz(r,     k0 + q2)),
                  *(const float2*)(A + swz(r + 8, k0 + q2)),
                  *(const float2*)(A + swz(r,     k0 + 8 + q2)),
                  *(const float2*)(A + swz(r + 8, k0 + 8 + q2)))
    }
}

__device__ __forceinline__
void mma_main_gmem(const float* __restrict__ A, const uint2* __restrict__ wh,
                   const uint2* __restrict__ wl, int wp, int lane, float c[4][4])
{
    const int rg = wp >> 2, cg = wp & 3;
    const int r = rg * 16 + (lane >> 2);
    const int q2 = (lane & 3) * 2;
    #pragma unroll
    for (int ks = 0; ks < 8; ++ks) {
        const int k0 = ks * 16;
        MMA_KSTEP(__ldg((const float2*)(A + (r    ) * CH + k0 + q2)),
                  __ldg((const float2*)(A + (r + 8) * CH + k0 + q2)),
                  __ldg((const float2*)(A + (r    ) * CH + k0 + 8 + q2)),
                  __ldg((const float2*)(A + (r + 8) * CH + k0 + 8 + q2)))
    }
}

__device__ __forceinline__
void mma_epi_smem(float c[4][4], const float* __restrict__ bias, int boff,
                  float* __restrict__ out_s, int wp, int lane)
{
    const int rg = wp >> 2, cg = wp & 3;
    const int r = rg * 16 + (lane >> 2);
    const int q2 = (lane & 3) * 2;
    #pragma unroll
    for (int nt = 0; nt < 4; ++nt) {
        const int col = cg * 32 + nt * 8 + q2;
        const float2 bv = *(const float2*)(bias + boff + col);
        *(float2*)(out_s + swz(r,     col)) = make_float2(c[nt][0] + bv.x, c[nt][1] + bv.y);
        *(float2*)(out_s + swz(r + 8, col)) = make_float2(c[nt][2] + bv.x, c[nt][3] + bv.y);
    }
}

// ---------------- kernel 2 ----------------
__global__ __launch_bounds__(NTHR, 2)
void k_main(const float* __restrict__ rpp,
            const float* __restrict__ q_b, const float* __restrict__ kv_b,
            const float* __restrict__ o_b, float* __restrict__ out)
{
    extern __shared__ float sm[];
    float* bufA = sm;            // q -> attn-out (per-head column reuse)
    float* bufB = bufA + 8192;   // xd2 -> v (in-place, barrier-protected)
    float* bufC = bufB + 8192;   // xd -> k
    float* sSim = bufC + 8192;   // 64x64 swizzled

    const int win = blockIdx.x;
    const int b   = win >> 10;
    const int wr  = win & 1023;
    const int wi  = wr >> 5;
    const int wj  = wr & 31;
    const int tid = threadIdx.x;
    const int wp  = tid >> 5, tx = tid & 31;

    // ---- inter-window bilinear blend -> bufC (xd) ----
    {
        const float ox = __ldg(g_oi + win * 2 + 0), oy = __ldg(g_oi + win * 2 + 1);
        const float gxp = (float)wj + ox, gyp = (float)wi + oy;
        const float x0f = floorf(gxp), y0f = floorf(gyp);
        const float fx = gxp - x0f, fy = gyp - y0f;
        const int x0 = (int)x0f, y0 = (int)y0f;
        const float wgt[4] = {(1.f - fx) * (1.f - fy), fx * (1.f - fy),
                              (1.f - fx) * fy,          fx * fy};
        const float4* nb[4];
        float nww[4];
        #pragma unroll
        for (int k = 0; k < 4; ++k) {
            const int xx = x0 + (k & 1), yy = y0 + (k >> 1);
            const bool valid = (xx >= 0) && (xx < W1G) && (yy >= 0) && (yy < W1G);
            nb[k]  = (const float4*)(valid ? (g_xw + (size_t)((b << 10) + (yy << 5) + xx) * P2 * CH)
                                           : g_xw);
            nww[k] = valid ? wgt[k] : 0.f;
        }
        float4* outv4 = (float4*)bufC;
        for (int i4 = tid; i4 < 2048; i4 += NTHR) {
            const float4 v0 = __ldg(nb[0] + i4), v1 = __ldg(nb[1] + i4);
            const float4 v2 = __ldg(nb[2] + i4), v3 = __ldg(nb[3] + i4);
            float4 r;
            r.x = nww[0]*v0.x + nww[1]*v1.x + nww[2]*v2.x + nww[3]*v3.x;
            r.y = nww[0]*v0.y + nww[1]*v1.y + nww[2]*v2.y + nww[3]*v3.y;
            r.z = nww[0]*v0.z + nww[1]*v1.z + nww[2]*v2.z + nww[3]*v3.z;
            r.w = nww[0]*v0.w + nww[1]*v1.w + nww[2]*v2.w + nww[3]*v3.w;
            outv4[swz4(i4 >> 5, i4 & 31)] = r;
        }
    }
    __syncthreads();

    // ---- intra-window gather bufC -> bufB (xd2) ----
    {
        const float4* inv4 = (const float4*)bufC;
        float4* outv4 = (float4*)bufB;
        #pragma unroll
        for (int it = 0; it < 4; ++it) {
            const int i4 = tid + it * NTHR;
            const int tok = i4 >> 5, c4 = i4 & 31;
            const int pi = tok >> 3, pj = tok & 7;
            const float o0 = __ldg(g_off + win * 128 + tok * 2);
            const float o1 = __ldg(g_off + win * 128 + tok * 2 + 1);
            const float gx2 = (float)pj + o0, gy2 = (float)pi + o1;
            const float xf = floorf(gx2), yf = floorf(gy2);
            const float fx = gx2 - xf, fy = gy2 - yf;
            const int x0 = (int)xf, y0 = (int)yf;
            const float ww[4] = {(1.f - fx) * (1.f - fy), fx * (1.f - fy),
                                 (1.f - fx) * fy,          fx * fy};
            float4 r = make_float4(0.f, 0.f, 0.f, 0.f);
            #pragma unroll
            for (int k = 0; k < 4; ++k) {
                const int xx = x0 + (k & 1), yy = y0 + (k >> 1);
                const bool valid = (xx >= 0) && (xx < WSZ) && (yy >= 0) && (yy < WSZ);
                const int idx = valid ? (yy * 8 + xx) : 0;
                const float wk = valid ? ww[k] : 0.f;
                const float4 a = inv4[swz4(idx, c4)];
                r.x = fmaf(wk, a.x, r.x);
                r.y = fmaf(wk, a.y, r.y);
                r.z = fmaf(wk, a.z, r.z);
                r.w = fmaf(wk, a.w, r.w);
            }
            outv4[swz4(tok, c4)] = r;
        }
    }
    __syncthreads();

    // ---- GEMMs on tensor cores (bf16x3) ----
    {   // k: bufB(xd2) -> bufC (xd dead)
        float c[4][4] = {};
        mma_main_smem(bufB, g_kfh, g_kfl, wp, tx, c);
        mma_epi_smem(c, kv_b, 0, bufC, wp, tx);
    }
    {   // q: gmem xw -> bufA
        float c[4][4] = {};
        mma_main_gmem(g_xw + (size_t)win * P2 * CH, g_qfh, g_qfl, wp, tx, c);
        mma_epi_smem(c, q_b, 0, bufA, wp, tx);
    }
    {   // v: bufB -> bufB in-place, block barrier between reads and writes
        float c[4][4] = {};
        mma_main_smem(bufB, g_vfh, g_vfl, wp, tx, c);
        __syncthreads();
        mma_epi_smem(c, kv_b, 128, bufB, wp, tx);
    }
    __syncthreads();

    // ---- attention on tensor cores (per head: QK -> softmax -> PV) ----
    const float scale = 0.17677669529663687f;
    const bool lastRow = (wi == W1G - 1), lastCol = (wj == W1G - 1);
    const int rg = wp >> 2, cg = wp & 3;
    const int rA = rg * 16 + (tx >> 2);
    const int q2 = (tx & 3) * 2;
    const int sr0 = wp * 4;

    for (int hh = 0; hh < NH; ++hh) {
        // -- QK: sim tile 16x16 per warp --
        {
            float c[2][4] = {};
            #pragma unroll
            for (int ks = 0; ks < 2; ++ks) {
                const int ch0 = hh * HD + ks * 16;
                unsigned ah0, al0, ah1, al1, ah2, al2, ah3, al3;
                split2(*(const float2*)(bufA + swz(rA,     ch0 + q2)),     ah0, al0);
                split2(*(const float2*)(bufA + swz(rA + 8, ch0 + q2)),     ah1, al1);
                split2(*(const float2*)(bufA + swz(rA,     ch0 + 8 + q2)), ah2, al2);
                split2(*(const float2*)(bufA + swz(rA + 8, ch0 + 8 + q2)), ah3, al3);
                #pragma unroll
                for (int nt = 0; nt < 2; ++nt) {
                    const int n = cg * 16 + nt * 8 + (tx >> 2);
                    unsigned bh0, bl0, bh1, bl1;
                    split2(*(const float2*)(bufC + swz(n, ch0 + q2)),     bh0, bl0);
                    split2(*(const float2*)(bufC + swz(n, ch0 + 8 + q2)), bh1, bl1);
                    mma_bf16(c[nt], ah0, ah1, ah2, ah3, bh0, bh1);
                    mma_bf16(c[nt], al0, al1, al2, al3, bh0, bh1);
                    mma_bf16(c[nt], ah0, ah1, ah2, ah3, bl0, bl1);
                }
            }
            const float* rb = rpp + hh * 225;
            #pragma unroll
            for (int nt = 0; nt < 2; ++nt) {
                const int col = cg * 16 + nt * 8 + q2;
                #pragma unroll
                for (int h2 = 0; h2 < 2; ++h2) {
                    const int i = rA + 8 * h2;
                    const int pi_i = i >> 3, pj_i = i & 7;
                    float vals[2];
                    #pragma unroll
                    for (int u = 0; u < 2; ++u) {
                        const int j = col + u;
                        const int pi_j = j >> 3, pj_j = j & 7;
                        const float bias = __ldg(rb + (pi_i - pi_j + 7) * 15 + (pj_i - pj_j + 7));
                        const bool msk = (lastRow && ((pi_i < 4) != (pi_j < 4)))
                                      || (lastCol && ((pj_i < 4) != (pj_j < 4)));
                        vals[u] = msk ? -CUDART_INF_F : fmaf(c[nt][2 * h2 + u], scale, bias);
                    }
                    *(float2*)(sSim + sswz(i, col)) = make_float2(vals[0], vals[1]);
                }
            }
        }
        __syncthreads();

        // -- softmax: warp owns rows sr0..sr0+3 --
        #pragma unroll
        for (int r = 0; r < 4; ++r) {
            const int i = sr0 + r;
            const float a = sSim[sswz(i, tx)], bb = sSim[sswz(i, tx + 32)];
            float m = fmaxf(a, bb);
            #pragma unroll
            for (int s2 = 16; s2 > 0; s2 >>= 1) m = fmaxf(m, __shfl_xor_sync(0xffffffffu, m, s2));
            const float e0 = __expf(a - m), e1 = __expf(bb - m);
            float s = e0 + e1;
            #pragma unroll
            for (int s2 = 16; s2 > 0; s2 >>= 1) s += __shfl_xor_sync(0xffffffffu, s, s2);
            const float inv = 1.f / s;
            sSim[sswz(i, tx)]      = e0 * inv;
            sSim[sswz(i, tx + 32)] = e1 * inv;
        }
        __syncthreads();

        // -- PV: out tile 16x8 per warp, cols hh*32 + cg*8 --
        {
            float c[4] = {};
            const int nB = hh * HD + cg * 8 + (tx >> 2);
            #pragma unroll
            for (int ks = 0; ks < 4; ++ks) {
                const int k0 = ks * 16;
                unsigned ah0, al0, ah1, al1, ah2, al2, ah3, al3;
                split2(*(const float2*)(sSim + sswz(rA,     k0 + q2)),     ah0, al0);
                split2(*(const float2*)(sSim + sswz(rA + 8, k0 + q2)),     ah1, al1);
                split2(*(const float2*)(sSim + sswz(rA,     k0 + 8 + q2)), ah2, al2);
                split2(*(const float2*)(sSim + sswz(rA + 8, k0 + 8 + q2)), ah3, al3);
                const float v00 = bufB[swz(k0 + q2,     nB)];
                const float v01 = bufB[swz(k0 + q2 + 1, nB)];
                const float v10 = bufB[swz(k0 + q2 + 8, nB)];
                const float v11 = bufB[swz(k0 + q2 + 9, nB)];
                const unsigned bh0 = prmt_hi(v00, v01);
                const unsigned bl0 = pack_rn(v00 - trunc_hi(v00), v01 - trunc_hi(v01));
                const unsigned bh1 = prmt_hi(v10, v11);
                const unsigned bl1 = pack_rn(v10 - trunc_hi(v10), v11 - trunc_hi(v11));
                mma_bf16(c, ah0, ah1, ah2, ah3, bh0, bh1);
                mma_bf16(c, al0, al1, al2, al3, bh0, bh1);
                mma_bf16(c, ah0, ah1, ah2, ah3, bl0, bl1);
            }
            const int colO = hh * HD + cg * 8 + q2;
            *(float2*)(bufA + swz(rA,     colO)) = make_float2(c[0], c[1]);
            *(float2*)(bufA + swz(rA + 8, colO)) = make_float2(c[2], c[3]);
        }
        __syncthreads();
    }

    // ---- o projection on tensor cores + un-shift scatter ----
    {
        float c[4][4] = {};
        mma_main_smem(bufA, g_ofh, g_ofl, wp, tx, c);
        #pragma unroll
        for (int nt = 0; nt < 4; ++nt) {
            const int col = cg * 32 + nt * 8 + q2;
            const float2 bv = *(const float2*)(o_b + col);
            #pragma unroll
            for (int h = 0; h < 2; ++h) {
                const int tok = rA + 8 * h;
                const int pi = tok >> 3, pj = tok & 7;
                const int rr = (wi * 8 + pi + SHIFT) & 255;
                const int cc = (wj * 8 + pj + SHIFT) & 255;
                float2 o;
                o.x = c[nt][2 * h + 0] + bv.x;
                o.y = c[nt][2 * h + 1] + bv.y;
                *(float2*)(out + (size_t)((((b << 8) + rr) << 8) + cc) * CH + col) = o;
            }
        }
    }
}

extern "C" void kernel_launch(void* const* d_in, const int* in_sizes, int n_in,
                              void* d_out, int out_size)
{
    const float* x    = (const float*)d_in[0];
    const float* rpp  = (const float*)d_in[1];
    const float* wi_w = (const float*)d_in[2];
    const float* wi_b = (const float*)d_in[3];
    const float* w1_w = (const float*)d_in[4];
    const float* w1_b = (const float*)d_in[5];
    const float* w2_w = (const float*)d_in[6];
    const float* w2_b = (const float*)d_in[7];
    const float* q_w  = (const float*)d_in[8];
    const float* q_b  = (const float*)d_in[9];
    const float* kv_w = (const float*)d_in[10];
    const float* kv_b = (const float*)d_in[11];
    const float* o_w  = (const float*)d_in[12];
    const float* o_b  = (const float*)d_in[13];
    float* out = (float*)d_out;

    const size_t smem2 = (size_t)(3 * 8192 + 4096) * sizeof(float);
    cudaFuncSetAttribute(k_main, cudaFuncAttributeMaxDynamicSharedMemorySize, (int)smem2);

    k_wfrag<<<16, 256>>>(q_w, kv_w, o_w);
    k_prep<<<NWIN, 256>>>(x, wi_w, wi_b, w1_w, w1_b, w2_w, w2_b);
    k_main<<<NWIN, NTHR, smem2>>>(rpp, q_b, kv_b, o_b, out);
}